// round 7
// baseline (speedup 1.0000x reference)
#include <cuda_runtime.h>
#include <cstdint>

#define B_   4
#define H_   8
#define LQ   1024
#define DH   64
#define KL   1024
#define NJ   33      // 2*MAX_REL_POS + 1
#define MAXREL 16
#define QT   2       // q-rows per block
#define TPAD 68      // table row stride (floats): 272B, 16B-aligned rows
#define SPAD 36      // sS row stride

__device__ __forceinline__ unsigned long long fma2(unsigned long long a,
                                                   unsigned long long b,
                                                   unsigned long long c) {
    unsigned long long d;
    asm("fma.rn.f32x2 %0, %1, %2, %3;" : "=l"(d) : "l"(a), "l"(b), "l"(c));
    return d;
}
__device__ __forceinline__ float2 unpack2(unsigned long long p) {
    unsigned int lo, hi;
    asm("mov.b64 {%0, %1}, %2;" : "=r"(lo), "=r"(hi) : "l"(p));
    return make_float2(__uint_as_float(lo), __uint_as_float(hi));
}

// ---------------------------------------------------------------------------
// Fused: per block (qBase=2 q-rows, batch b):
//   A) load table[33][64] + query[2][8][64] to smem
//   B) S[ql][h][j] = dot(query[ql][h][:], table[j][:])   (264 threads, f32x2)
//   C) out[b,h,q,k] = S[ql][h][clip(ts[k]-ts[q])+16]     (round-3 gather)
// ---------------------------------------------------------------------------
__global__ void __launch_bounds__(288) fused_relpe_kernel(
    const float* __restrict__ query,
    const float* __restrict__ table,
    const int*   __restrict__ time_ids,
    float* __restrict__ out)
{
    __shared__ __align__(16) float tS[NJ][TPAD];       // table rows, d-contig
    __shared__ __align__(16) float qS[QT][H_][DH];     // query rows, d-contig
    __shared__ float sS[QT][H_][SPAD];                 // S values
    __shared__ int   s_tq[QT];

    const int tid   = threadIdx.x;
    const int qBase = blockIdx.x * QT;
    const int b     = blockIdx.y;

    // --- Phase A: loads ---
    // table: 33*64/4 = 528 float4
    for (int i = tid; i < NJ * DH / 4; i += 288) {
        float4 v = ((const float4*)table)[i];
        int j  = i >> 4;
        int d0 = (i & 15) << 2;
        *(float4*)(&tS[j][d0]) = v;
    }
    // query: QT*8*64/4 = 256 float4.  i = h*32 + ql*16 + d4
    for (int i = tid; i < QT * H_ * DH / 4; i += 288) {
        int h  = i >> 5;
        int r  = i & 31;
        int ql = r >> 4;
        int d0 = (r & 15) << 2;
        float4 v = *(const float4*)(query +
            (size_t)(((b * H_ + h) << 10) + qBase + ql) * DH + d0);
        *(float4*)(&qS[ql][h][d0]) = v;
    }
    const int* tsb = time_ids + b * KL;
    if (tid < QT) s_tq[tid] = tsb[qBase + tid];
    __syncthreads();

    // --- Phase B: S[ql][h][j] via packed f32x2 dots ---
    if (tid < H_ * NJ) {
        const int h = tid / NJ;
        const int j = tid - h * NJ;
        const unsigned long long* tp = (const unsigned long long*)(&tS[j][0]);
        #pragma unroll
        for (int ql = 0; ql < QT; ql++) {
            const unsigned long long* qp =
                (const unsigned long long*)(&qS[ql][h][0]);
            unsigned long long accA = 0ull, accB = 0ull;
            #pragma unroll
            for (int d2 = 0; d2 < DH / 4; d2++) {
                ulonglong2 tv = ((const ulonglong2*)tp)[d2];
                ulonglong2 qv = ((const ulonglong2*)qp)[d2];
                accA = fma2(qv.x, tv.x, accA);
                accB = fma2(qv.y, tv.y, accB);
            }
            float2 a = unpack2(accA);
            float2 c = unpack2(accB);
            sS[ql][h][j] = (a.x + a.y) + (c.x + c.y);
        }
    }
    __syncthreads();

    // --- Phase C: gather + store (round-3 structure, known 28-reg shape) ---
    if (tid < 256) {
        const int k0 = tid * 4;
        const int4 tk = *(const int4*)(tsb + k0);

        #pragma unroll
        for (int ql = 0; ql < QT; ql++) {
            const int tq = s_tq[ql];
            int i0 = min(max(tk.x - tq, -MAXREL), MAXREL) + MAXREL;
            int i1 = min(max(tk.y - tq, -MAXREL), MAXREL) + MAXREL;
            int i2 = min(max(tk.z - tq, -MAXREL), MAXREL) + MAXREL;
            int i3 = min(max(tk.w - tq, -MAXREL), MAXREL) + MAXREL;

            float* op = out +
                ((size_t)(((b * H_) << 10) + qBase + ql) << 10) + k0;
            #pragma unroll
            for (int h = 0; h < H_; h++) {
                float4 o = make_float4(sS[ql][h][i0], sS[ql][h][i1],
                                       sS[ql][h][i2], sS[ql][h][i3]);
                *(float4*)(op + ((size_t)h << 20)) = o;
            }
        }
    }
}

// ---------------------------------------------------------------------------
extern "C" void kernel_launch(void* const* d_in, const int* in_sizes, int n_in,
                              void* d_out, int out_size)
{
    const float* query    = (const float*)d_in[0];   // [4,8,1024,64]
    const float* table    = (const float*)d_in[1];   // [33,64]
    const int*   time_ids = (const int*)d_in[2];     // [4,1024] int32
    float*       out      = (float*)d_out;           // [4,8,1024,1024]

    dim3 grid(LQ / QT, B_);
    fused_relpe_kernel<<<grid, 288>>>(query, table, time_ids, out);
}

// round 8
// speedup vs baseline: 1.0910x; 1.0910x over previous
#include <cuda_runtime.h>
#include <cstdint>

#define B_   4
#define H_   8
#define LQ   1024
#define DH   64
#define KL   1024
#define NJ   33      // 2*MAX_REL_POS + 1
#define MAXREL 16
#define QT   2       // q-rows per block
#define TPAD 68      // table row stride (floats), 16B-aligned rows
#define SPAD 36      // sS row stride

// ---------------------------------------------------------------------------
// Fused: per block (2 q-rows, batch b):
//   A) load table[33][64] + query[2][8][64] to smem
//   B) S[ql][h][j] = dot(query[ql][h][:], table[j][:])  (strided, scalar FMA)
//   C) out[b,h,q,k] = S[ql][h][clip(ts[k]-ts[q])+16]    (round-3 gather body)
// ---------------------------------------------------------------------------
__global__ void __launch_bounds__(256, 6) fused_relpe_kernel(
    const float* __restrict__ query,
    const float* __restrict__ table,
    const int*   __restrict__ time_ids,
    float* __restrict__ out)
{
    __shared__ __align__(16) float tS[NJ][TPAD];     // table rows, d-contig
    __shared__ __align__(16) float qS[QT][H_][DH];   // query rows, d-contig
    __shared__ float sS[QT][H_][SPAD];               // S values
    __shared__ int   s_tq[QT];

    const int tid   = threadIdx.x;
    const int qBase = blockIdx.x * QT;
    const int b     = blockIdx.y;

    // --- Phase A: loads ---
    for (int i = tid; i < NJ * DH / 4; i += 256) {       // 528 float4
        float4 v = ((const float4*)table)[i];
        int j  = i >> 4;
        int d0 = (i & 15) << 2;
        *(float4*)(&tS[j][d0]) = v;
    }
    for (int i = tid; i < QT * H_ * DH / 4; i += 256) {  // 256 float4
        int h  = i >> 5;
        int r  = i & 31;
        int ql = r >> 4;
        int d0 = (r & 15) << 2;
        float4 v = *(const float4*)(query +
            (size_t)(((b * H_ + h) << 10) + qBase + ql) * DH + d0);
        *(float4*)(&qS[ql][h][d0]) = v;
    }
    const int* tsb = time_ids + b * KL;
    if (tid < QT) s_tq[tid] = tsb[qBase + tid];
    __syncthreads();

    // --- Phase B: 2*264 dots, strided over 256 threads, low-reg scalar form ---
    for (int i = tid; i < H_ * NJ; i += 256) {
        const int h = i / NJ;
        const int j = i - h * NJ;
        #pragma unroll
        for (int ql = 0; ql < QT; ql++) {
            float a0 = 0.f, a1 = 0.f, a2 = 0.f, a3 = 0.f;
            #pragma unroll 4
            for (int d4 = 0; d4 < DH / 4; d4++) {
                float4 tv = *(const float4*)(&tS[j][d4 << 2]);
                float4 qv = *(const float4*)(&qS[ql][h][d4 << 2]);
                a0 += qv.x * tv.x;
                a1 += qv.y * tv.y;
                a2 += qv.z * tv.z;
                a3 += qv.w * tv.w;
            }
            sS[ql][h][j] = (a0 + a1) + (a2 + a3);
        }
    }
    __syncthreads();

    // --- Phase C: gather + store (round-3 body) ---
    const int k0 = tid * 4;
    const int4 tk = *(const int4*)(tsb + k0);

    #pragma unroll
    for (int ql = 0; ql < QT; ql++) {
        const int tq = s_tq[ql];
        int i0 = min(max(tk.x - tq, -MAXREL), MAXREL) + MAXREL;
        int i1 = min(max(tk.y - tq, -MAXREL), MAXREL) + MAXREL;
        int i2 = min(max(tk.z - tq, -MAXREL), MAXREL) + MAXREL;
        int i3 = min(max(tk.w - tq, -MAXREL), MAXREL) + MAXREL;

        float* op = out + ((size_t)(((b * H_) << 10) + qBase + ql) << 10) + k0;
        #pragma unroll
        for (int h = 0; h < H_; h++) {
            float4 o = make_float4(sS[ql][h][i0], sS[ql][h][i1],
                                   sS[ql][h][i2], sS[ql][h][i3]);
            *(float4*)(op + ((size_t)h << 20)) = o;
        }
    }
}

// ---------------------------------------------------------------------------
extern "C" void kernel_launch(void* const* d_in, const int* in_sizes, int n_in,
                              void* d_out, int out_size)
{
    const float* query    = (const float*)d_in[0];   // [4,8,1024,64]
    const float* table    = (const float*)d_in[1];   // [33,64]
    const int*   time_ids = (const int*)d_in[2];     // [4,1024] int32
    float*       out      = (float*)d_out;           // [4,8,1024,1024]

    dim3 grid(LQ / QT, B_);
    fused_relpe_kernel<<<grid, 256>>>(query, table, time_ids, out);
}